// round 2
// baseline (speedup 1.0000x reference)
#include <cuda_runtime.h>
#include <math.h>

#define NA 192
#define TT 80
#define NC 5
#define THREADS 256

__global__ void __launch_bounds__(THREADS)
veh_coll_kernel(const float* __restrict__ traj,       // (NA, T, 4)
                const float* __restrict__ cent,       // (NA, NC, 4)
                const float* __restrict__ pd,         // (NA, NA)
                float* __restrict__ out)              // penalties then mask
{
    const int t   = blockIdx.y;
    const int tid = threadIdx.x;

    __shared__ float2 w[NC][NA];

    // ---- build world circle centers for all 192 agents at time t ----
    if (tid < NA) {
        const int a = tid;
        const float4 tr = *reinterpret_cast<const float4*>(traj + ((size_t)a * TT + t) * 4);
        float hx = tr.z, hy = tr.w;
        const float inv = rsqrtf(hx * hx + hy * hy);
        hx *= inv; hy *= inv;
        const float x = tr.x, y = tr.y;
        #pragma unroll
        for (int c = 0; c < NC; ++c) {
            // centroids row layout: (cx, cy, 1, 0)
            const float2 cc = *reinterpret_cast<const float2*>(cent + ((size_t)a * NC + c) * 4);
            float2 wc;
            wc.x = fmaf(hx, cc.x, fmaf(-hy, cc.y, x));
            wc.y = fmaf(hy, cc.x, fmaf( hx, cc.y, y));
            w[c][a] = wc;
        }
    }
    __syncthreads();

    const int idx = blockIdx.x * THREADS + tid;   // pair index within this t
    if (idx >= NA * NA) return;
    const int i = idx / NA;
    const int j = idx - i * NA;

    // hoist i's circles to registers (warp-uniform i -> broadcast LDS)
    float ixr[NC], iyr[NC];
    #pragma unroll
    for (int c = 0; c < NC; ++c) {
        const float2 wi = w[c][i];
        ixr[c] = wi.x; iyr[c] = wi.y;
    }

    float mind2 = 3.4e38f;
    #pragma unroll
    for (int d = 0; d < NC; ++d) {
        const float2 wj = w[d][j];   // consecutive j, 8B stride: conflict-free
        #pragma unroll
        for (int c = 0; c < NC; ++c) {
            const float dx = ixr[c] - wj.x;
            const float dy = iyr[c] - wj.y;
            const float d2 = fmaf(dx, dx, dy * dy);
            mind2 = fminf(mind2, d2);
        }
    }

    const float mind = sqrtf(mind2);
    const float p    = pd[idx];
    const size_t o   = (size_t)t * (NA * NA) + idx;

    out[o] = 1.0f - mind / p;

    // off_diag_mask is exactly ~eye(NA) by construction -> use (i != j)
    const bool coll = (mind <= p) && (i != j);
    out[(size_t)TT * (NA * NA) + o] = coll ? 1.0f : 0.0f;
}

extern "C" void kernel_launch(void* const* d_in, const int* in_sizes, int n_in,
                              void* d_out, int out_size)
{
    const float* traj = (const float*)d_in[0];   // (192,80,4)
    const float* cent = (const float*)d_in[1];   // (192,5,4)
    const float* pd   = (const float*)d_in[2];   // (192,192)

    dim3 grid((NA * NA + THREADS - 1) / THREADS, TT);  // (144, 80)
    veh_coll_kernel<<<grid, THREADS>>>(traj, cent, pd, (float*)d_out);
}

// round 3
// speedup vs baseline: 1.2399x; 1.2399x over previous
#include <cuda_runtime.h>
#include <math.h>

#define NA 192
#define TT 80
#define NC 5
#define THREADS 256
#define BLOCKS_PER_T 24
#define CHUNKS 6            // 192*192 / 256 / BLOCKS_PER_T

// world-frame circle centers, layout [t][c][a], built once per step
__device__ float2 g_w[TT * NC * NA];

// ---- kernel A: one thread per (t, a): normalize heading, rotate circles ----
__global__ void __launch_bounds__(256)
build_w_kernel(const float* __restrict__ traj,   // (NA, T, 4)
               const float* __restrict__ cent)   // (NA, NC, 4)
{
    const int n = blockIdx.x * blockDim.x + threadIdx.x;
    if (n >= TT * NA) return;
    const int t = n / NA;
    const int a = n - t * NA;

    const float4 tr = *reinterpret_cast<const float4*>(traj + ((size_t)a * TT + t) * 4);
    float hx = tr.z, hy = tr.w;
    const float inv = rsqrtf(hx * hx + hy * hy);
    hx *= inv; hy *= inv;

    #pragma unroll
    for (int c = 0; c < NC; ++c) {
        const float2 cc = *reinterpret_cast<const float2*>(cent + ((size_t)a * NC + c) * 4);
        float2 wc;
        wc.x = fmaf(hx, cc.x, fmaf(-hy, cc.y, tr.x));
        wc.y = fmaf(hy, cc.x, fmaf( hx, cc.y, tr.y));
        g_w[((size_t)t * NC + c) * NA + a] = wc;   // coalesced in a
    }
}

// ---- kernel B: pair distances; block loads slab for its t, loops 6 chunks ----
__global__ void __launch_bounds__(THREADS)
pairs_kernel(const float* __restrict__ pd,   // (NA, NA)
             float* __restrict__ out)        // penalties then mask
{
    const int t   = blockIdx.y;
    const int tid = threadIdx.x;

    __shared__ float2 w[NC * NA];   // 7.5 KB

    // coalesced slab copy: 480 float4
    {
        const float4* __restrict__ src = reinterpret_cast<const float4*>(g_w + (size_t)t * NC * NA);
        float4* dst = reinterpret_cast<float4*>(w);
        #pragma unroll
        for (int k = tid; k < NC * NA / 2; k += THREADS) dst[k] = src[k];
    }
    __syncthreads();

    const size_t tbase = (size_t)t * (NA * NA);

    #pragma unroll
    for (int q = 0; q < CHUNKS; ++q) {
        const int idx = (q * BLOCKS_PER_T + blockIdx.x) * THREADS + tid;  // < NA*NA exactly
        const int i = idx / NA;
        const int j = idx - i * NA;

        // i warp-uniform (32 | 192): broadcast LDS
        float ixr[NC], iyr[NC];
        #pragma unroll
        for (int c = 0; c < NC; ++c) {
            const float2 wi = w[c * NA + i];
            ixr[c] = wi.x; iyr[c] = wi.y;
        }

        float m[NC];
        #pragma unroll
        for (int d = 0; d < NC; ++d) {
            const float2 wj = w[d * NA + j];   // stride-1 j: conflict-free
            float md = 3.4e38f;
            #pragma unroll
            for (int c = 0; c < NC; ++c) {
                const float dx = ixr[c] - wj.x;
                const float dy = iyr[c] - wj.y;
                const float d2 = fmaf(dx, dx, dy * dy);
                md = fminf(md, d2);
            }
            m[d] = md;
        }
        // tree reduce the 5 independent chains
        const float m01 = fminf(m[0], m[1]);
        const float m23 = fminf(m[2], m[3]);
        const float mind2 = fminf(fminf(m01, m23), m[4]);

        const float mind = sqrtf(mind2);
        const float p    = pd[idx];
        const size_t o   = tbase + idx;

        out[o] = 1.0f - mind / p;

        // off_diag_mask == ~eye(NA) by construction
        const bool coll = (mind <= p) && (i != j);
        out[(size_t)TT * (NA * NA) + o] = coll ? 1.0f : 0.0f;
    }
}

extern "C" void kernel_launch(void* const* d_in, const int* in_sizes, int n_in,
                              void* d_out, int out_size)
{
    const float* traj = (const float*)d_in[0];   // (192,80,4)
    const float* cent = (const float*)d_in[1];   // (192,5,4)
    const float* pd   = (const float*)d_in[2];   // (192,192)

    const int nA = TT * NA;
    build_w_kernel<<<(nA + 255) / 256, 256>>>(traj, cent);

    dim3 grid(BLOCKS_PER_T, TT);   // (24, 80)
    pairs_kernel<<<grid, THREADS>>>(pd, (float*)d_out);
}

// round 4
// speedup vs baseline: 1.4992x; 1.2092x over previous
#include <cuda_runtime.h>
#include <math.h>

#define NA 192
#define TT 80
#define NC 5
#define THREADS 256
#define BLOCKS_PER_T 12
#define CHUNKS 3           // 36864 pairs / (12 blocks * 256 thr * 4 pairs) = 3
#define PLANE (NC * NA)    // 960 floats per coordinate plane

// world-frame circle centers per t: [t][0][c*NA+a] = x, [t][1][...] = y
__device__ float g_w[TT * 2 * PLANE];

// packed {-v, -v}
#define PACK_NEG2(dst, v) \
    asm("mov.b64 %0, {%1, %1};" : "=l"(dst) : "f"(-(v)))

// two squared distances (packed) + running scalar mins
#define CIRC2(mlo, mhi, xj, nxi, yj, nyi)                         \
    asm("{\n\t"                                                   \
        ".reg .b64 dx, dy, d2;\n\t"                               \
        ".reg .f32 lo, hi;\n\t"                                   \
        "add.rn.f32x2 dx, %2, %3;\n\t"                            \
        "add.rn.f32x2 dy, %4, %5;\n\t"                            \
        "mul.rn.f32x2 d2, dy, dy;\n\t"                            \
        "fma.rn.f32x2 d2, dx, dx, d2;\n\t"                        \
        "mov.b64 {lo, hi}, d2;\n\t"                               \
        "min.f32 %0, %0, lo;\n\t"                                 \
        "min.f32 %1, %1, hi;\n\t"                                 \
        "}"                                                       \
        : "+f"(mlo), "+f"(mhi)                                    \
        : "l"(xj), "l"(nxi), "l"(yj), "l"(nyi))

// ---- kernel A: one thread per (t, a): normalize heading, rotate circles ----
__global__ void __launch_bounds__(256)
build_w_kernel(const float* __restrict__ traj,   // (NA, T, 4)
               const float* __restrict__ cent)   // (NA, NC, 4)
{
    const int n = blockIdx.x * blockDim.x + threadIdx.x;
    if (n >= TT * NA) return;
    const int t = n / NA;
    const int a = n - t * NA;

    const float4 tr = *reinterpret_cast<const float4*>(traj + ((size_t)a * TT + t) * 4);
    float hx = tr.z, hy = tr.w;
    const float inv = rsqrtf(hx * hx + hy * hy);
    hx *= inv; hy *= inv;

    float* __restrict__ wx = g_w + (size_t)t * 2 * PLANE;
    float* __restrict__ wy = wx + PLANE;

    #pragma unroll
    for (int c = 0; c < NC; ++c) {
        const float2 cc = *reinterpret_cast<const float2*>(cent + ((size_t)a * NC + c) * 4);
        wx[c * NA + a] = fmaf(hx, cc.x, fmaf(-hy, cc.y, tr.x));   // coalesced in a
        wy[c * NA + a] = fmaf(hy, cc.x, fmaf( hx, cc.y, tr.y));
    }
}

// ---- kernel B: 4 consecutive j per thread, packed f32x2 distance math ----
__global__ void __launch_bounds__(THREADS)
pairs_kernel(const float* __restrict__ pd,   // (NA, NA)
             float* __restrict__ out)        // penalties then mask
{
    const int t   = blockIdx.y;
    const int tid = threadIdx.x;

    __shared__ __align__(16) float s[2 * PLANE];   // 7.5 KB: wx then wy
    const float* __restrict__ swx = s;
    const float* __restrict__ swy = s + PLANE;

    // coalesced slab copy: 480 float4
    {
        const float4* __restrict__ src = reinterpret_cast<const float4*>(g_w + (size_t)t * 2 * PLANE);
        float4* dst = reinterpret_cast<float4*>(s);
        #pragma unroll
        for (int k = tid; k < 2 * PLANE / 4; k += THREADS) dst[k] = src[k];
    }
    __syncthreads();

    const size_t tbase = (size_t)t * (NA * NA);

    #pragma unroll 1
    for (int q = 0; q < CHUNKS; ++q) {
        const int quad = (q * BLOCKS_PER_T + blockIdx.x) * THREADS + tid;  // < 9216
        const int i  = quad / (NA / 4);            // 48 quads per row
        const int j0 = (quad - i * (NA / 4)) * 4;

        // packed {-xi,-xi}, {-yi,-yi} per circle (broadcast LDS, warp-mostly-uniform i)
        unsigned long long nxi[NC], nyi[NC];
        #pragma unroll
        for (int c = 0; c < NC; ++c) {
            PACK_NEG2(nxi[c], swx[c * NA + i]);
            PACK_NEG2(nyi[c], swy[c * NA + i]);
        }

        float m0 = 3.4e38f, m1 = 3.4e38f, m2 = 3.4e38f, m3 = 3.4e38f;

        #pragma unroll
        for (int d = 0; d < NC; ++d) {
            // 4 consecutive j coords: one LDS.128 each; register pairs are f32x2
            const ulonglong2 xj = *reinterpret_cast<const ulonglong2*>(swx + d * NA + j0);
            const ulonglong2 yj = *reinterpret_cast<const ulonglong2*>(swy + d * NA + j0);
            #pragma unroll
            for (int c = 0; c < NC; ++c) {
                CIRC2(m0, m1, xj.x, nxi[c], yj.x, nyi[c]);
                CIRC2(m2, m3, xj.y, nxi[c], yj.y, nyi[c]);
            }
        }

        const float4 p4 = *reinterpret_cast<const float4*>(pd + i * NA + j0);
        float mv[4] = {m0, m1, m2, m3};
        const float pv[4] = {p4.x, p4.y, p4.z, p4.w};
        float4 pen, msk;
        float* penp = &pen.x;
        float* mskp = &msk.x;

        #pragma unroll
        for (int k = 0; k < 4; ++k) {
            const float m2e = mv[k] + 1e-30f;      // diagonal-zero guard
            float r, rcp;
            asm("rsqrt.approx.f32 %0, %1;" : "=f"(r)   : "f"(m2e));
            asm("rcp.approx.f32 %0, %1;"   : "=f"(rcp) : "f"(pv[k]));
            const float mind = m2e * r;
            penp[k] = fmaf(-mind, rcp, 1.0f);
            mskp[k] = (mind <= pv[k] && i != j0 + k) ? 1.0f : 0.0f;
        }

        const size_t o = tbase + (size_t)quad * 4;
        *reinterpret_cast<float4*>(out + o) = pen;
        *reinterpret_cast<float4*>(out + (size_t)TT * (NA * NA) + o) = msk;
    }
}

extern "C" void kernel_launch(void* const* d_in, const int* in_sizes, int n_in,
                              void* d_out, int out_size)
{
    const float* traj = (const float*)d_in[0];   // (192,80,4)
    const float* cent = (const float*)d_in[1];   // (192,5,4)
    const float* pd   = (const float*)d_in[2];   // (192,192)

    const int nA = TT * NA;
    build_w_kernel<<<(nA + 255) / 256, 256>>>(traj, cent);

    dim3 grid(BLOCKS_PER_T, TT);   // (12, 80)
    pairs_kernel<<<grid, THREADS>>>(pd, (float*)d_out);
}

// round 6
// speedup vs baseline: 1.5061x; 1.0046x over previous
#include <cuda_runtime.h>
#include <math.h>

#define NA 192
#define TT 80
#define NC 5
#define THREADS 256
#define BLOCKS_PER_T 36     // 36864 pairs / (256 thr * 4 pairs)
#define PLANE (NC * NA)     // 960 floats per coordinate plane

// world circle centers per t: [t][0][c*NA+a]=x, [t][1][..]=y
__device__ float g_w[TT * 2 * PLANE];
__device__ float g_invpd[NA * NA];
__device__ float g_pd2[NA * NA];

// packed {-v, -v}
#define PACK_NEG2(dst, v) \
    asm("mov.b64 %0, {%1, %1};" : "=l"(dst) : "f"(-(v)))

// two squared distances (packed f32x2) + scalar running mins on the halves
#define CIRC2(mlo, mhi, xj, nxi, yj, nyi)                         \
    asm("{\n\t"                                                   \
        ".reg .b64 dx, dy, d2;\n\t"                               \
        ".reg .f32 lo, hi;\n\t"                                   \
        "add.rn.f32x2 dx, %2, %3;\n\t"                            \
        "add.rn.f32x2 dy, %4, %5;\n\t"                            \
        "mul.rn.f32x2 d2, dy, dy;\n\t"                            \
        "fma.rn.f32x2 d2, dx, dx, d2;\n\t"                        \
        "mov.b64 {lo, hi}, d2;\n\t"                               \
        "min.f32 %0, %0, lo;\n\t"                                 \
        "min.f32 %1, %1, hi;\n\t"                                 \
        "}"                                                       \
        : "+f"(mlo), "+f"(mhi)                                    \
        : "l"(xj), "l"(nxi), "l"(yj), "l"(nyi))

// ---- prep: blocks [0,60): build circles; blocks [60,204): pd transforms ----
__global__ void __launch_bounds__(256)
prep_kernel(const float* __restrict__ traj,   // (NA, T, 4)
            const float* __restrict__ cent,   // (NA, NC, 4)
            const float* __restrict__ pd)     // (NA, NA)
{
    const int bid = blockIdx.x;
    if (bid < 60) {
        const int n = bid * 256 + threadIdx.x;   // < 15360 exactly
        const int t = n / NA;
        const int a = n - t * NA;

        const float4 tr = *reinterpret_cast<const float4*>(traj + ((size_t)a * TT + t) * 4);
        float hx = tr.z, hy = tr.w;
        const float inv = rsqrtf(hx * hx + hy * hy);
        hx *= inv; hy *= inv;

        float* __restrict__ wx = g_w + (size_t)t * 2 * PLANE;
        float* __restrict__ wy = wx + PLANE;
        #pragma unroll
        for (int c = 0; c < NC; ++c) {
            const float2 cc = *reinterpret_cast<const float2*>(cent + ((size_t)a * NC + c) * 4);
            wx[c * NA + a] = fmaf(hx, cc.x, fmaf(-hy, cc.y, tr.x));
            wy[c * NA + a] = fmaf(hy, cc.x, fmaf( hx, cc.y, tr.y));
        }
    } else {
        const int k = (bid - 60) * 256 + threadIdx.x;  // < 36864 exactly
        const float p = pd[k];
        g_invpd[k] = 1.0f / p;
        g_pd2[k]   = p * p;
    }
}

// ---- pairs: 4 consecutive j per thread, packed f32x2 distance math ----
__global__ void __launch_bounds__(THREADS)
pairs_kernel(float* __restrict__ out)
{
    const int t   = blockIdx.y;
    const int tid = threadIdx.x;

    __shared__ __align__(16) float s[2 * PLANE];   // 7.5 KB: wx then wy
    const float* __restrict__ swx = s;
    const float* __restrict__ swy = s + PLANE;

    {
        const float4* __restrict__ src = reinterpret_cast<const float4*>(g_w + (size_t)t * 2 * PLANE);
        float4* dst = reinterpret_cast<float4*>(s);
        #pragma unroll
        for (int k = tid; k < 2 * PLANE / 4; k += THREADS) dst[k] = src[k];
    }
    __syncthreads();

    const int quad = blockIdx.x * THREADS + tid;   // < 9216
    const int i  = quad / (NA / 4);
    const int j0 = (quad - i * (NA / 4)) * 4;
    const int idx = quad * 4;                      // == i*NA + j0

    // packed {-xi,-xi},{-yi,-yi} per circle (broadcast LDS)
    unsigned long long nxi[NC], nyi[NC];
    #pragma unroll
    for (int c = 0; c < NC; ++c) {
        PACK_NEG2(nxi[c], swx[c * NA + i]);
        PACK_NEG2(nyi[c], swy[c * NA + i]);
    }

    // scalar min accumulators split by c-parity: shorter RAW chains
    float m0a = 3.4e38f, m1a = 3.4e38f, m2a = 3.4e38f, m3a = 3.4e38f;
    float m0b = 3.4e38f, m1b = 3.4e38f, m2b = 3.4e38f, m3b = 3.4e38f;

    #pragma unroll
    for (int d = 0; d < NC; ++d) {
        const ulonglong2 xj = *reinterpret_cast<const ulonglong2*>(swx + d * NA + j0);
        const ulonglong2 yj = *reinterpret_cast<const ulonglong2*>(swy + d * NA + j0);
        #pragma unroll
        for (int c = 0; c < NC; ++c) {
            if (c & 1) {
                CIRC2(m0b, m1b, xj.x, nxi[c], yj.x, nyi[c]);
                CIRC2(m2b, m3b, xj.y, nxi[c], yj.y, nyi[c]);
            } else {
                CIRC2(m0a, m1a, xj.x, nxi[c], yj.x, nyi[c]);
                CIRC2(m2a, m3a, xj.y, nxi[c], yj.y, nyi[c]);
            }
        }
    }

    float mv[4];
    mv[0] = fminf(m0a, m0b);
    mv[1] = fminf(m1a, m1b);
    mv[2] = fminf(m2a, m2b);
    mv[3] = fminf(m3a, m3b);

    const float4 ip4 = *reinterpret_cast<const float4*>(g_invpd + idx);
    const float4 p24 = *reinterpret_cast<const float4*>(g_pd2 + idx);
    const float ipv[4] = {ip4.x, ip4.y, ip4.z, ip4.w};
    const float p2v[4] = {p24.x, p24.y, p24.z, p24.w};

    float4 pen, msk;
    float* penp = &pen.x;
    float* mskp = &msk.x;
    #pragma unroll
    for (int k = 0; k < 4; ++k) {
        const float m2e = mv[k] + 1e-30f;      // diagonal-zero guard for rsqrt
        float r;
        asm("rsqrt.approx.f32 %0, %1;" : "=f"(r) : "f"(m2e));
        const float mind = m2e * r;            // = sqrt(m2e)
        penp[k] = fmaf(-mind, ipv[k], 1.0f);
        // sqrt monotone: mind <= p  <=>  m2 <= p^2 ; diagonal excluded by i != j
        mskp[k] = (mv[k] <= p2v[k] && i != j0 + k) ? 1.0f : 0.0f;
    }

    const size_t o = (size_t)t * (NA * NA) + idx;
    *reinterpret_cast<float4*>(out + o) = pen;
    *reinterpret_cast<float4*>(out + (size_t)TT * (NA * NA) + o) = msk;
}

extern "C" void kernel_launch(void* const* d_in, const int* in_sizes, int n_in,
                              void* d_out, int out_size)
{
    const float* traj = (const float*)d_in[0];   // (192,80,4)
    const float* cent = (const float*)d_in[1];   // (192,5,4)
    const float* pd   = (const float*)d_in[2];   // (192,192)

    prep_kernel<<<204, 256>>>(traj, cent, pd);

    dim3 grid(BLOCKS_PER_T, TT);   // (36, 80)
    pairs_kernel<<<grid, THREADS>>>((float*)d_out);
}

// round 7
// speedup vs baseline: 1.8634x; 1.2372x over previous
#include <cuda_runtime.h>
#include <math.h>

#define NA 192
#define TT 80
#define NC 5
#define THREADS 256
#define NTILE 21            // upper-triangular 32x32 tiles of 192x192
#define PLANE (NC * NA)     // 960 floats per coordinate plane
#define TP 33               // transpose tile pitch (conflict-free)

// world circle centers per t: [t][0][c*NA+a]=x, [t][1][..]=y
__device__ float g_w[TT * 2 * PLANE];
__device__ float g_invpd[NA * NA];
__device__ float g_pd2[NA * NA];

__constant__ int c_bi[NTILE] = {0,0,0,0,0,0, 1,1,1,1,1, 2,2,2,2, 3,3,3, 4,4, 5};
__constant__ int c_bj[NTILE] = {0,1,2,3,4,5, 1,2,3,4,5, 2,3,4,5, 3,4,5, 4,5, 5};

// packed {-v, -v}
#define PACK_NEG2(dst, v) \
    asm("mov.b64 %0, {%1, %1};" : "=l"(dst) : "f"(-(v)))

// two squared distances (packed f32x2) + scalar running mins on the halves
#define CIRC2(mlo, mhi, xj, nxi, yj, nyi)                         \
    asm("{\n\t"                                                   \
        ".reg .b64 dx, dy, d2;\n\t"                               \
        ".reg .f32 lo, hi;\n\t"                                   \
        "add.rn.f32x2 dx, %2, %3;\n\t"                            \
        "add.rn.f32x2 dy, %4, %5;\n\t"                            \
        "mul.rn.f32x2 d2, dy, dy;\n\t"                            \
        "fma.rn.f32x2 d2, dx, dx, d2;\n\t"                        \
        "mov.b64 {lo, hi}, d2;\n\t"                               \
        "min.f32 %0, %0, lo;\n\t"                                 \
        "min.f32 %1, %1, hi;\n\t"                                 \
        "}"                                                       \
        : "+f"(mlo), "+f"(mhi)                                    \
        : "l"(xj), "l"(nxi), "l"(yj), "l"(nyi))

// ---- prep: blocks [0,60): build circles; blocks [60,204): pd transforms ----
__global__ void __launch_bounds__(256)
prep_kernel(const float* __restrict__ traj,   // (NA, T, 4)
            const float* __restrict__ cent,   // (NA, NC, 4)
            const float* __restrict__ pd)     // (NA, NA)
{
    const int bid = blockIdx.x;
    if (bid < 60) {
        const int n = bid * 256 + threadIdx.x;   // < 15360 exactly
        const int t = n / NA;
        const int a = n - t * NA;

        const float4 tr = *reinterpret_cast<const float4*>(traj + ((size_t)a * TT + t) * 4);
        float hx = tr.z, hy = tr.w;
        const float inv = rsqrtf(hx * hx + hy * hy);
        hx *= inv; hy *= inv;

        float* __restrict__ wx = g_w + (size_t)t * 2 * PLANE;
        float* __restrict__ wy = wx + PLANE;
        #pragma unroll
        for (int c = 0; c < NC; ++c) {
            const float2 cc = *reinterpret_cast<const float2*>(cent + ((size_t)a * NC + c) * 4);
            wx[c * NA + a] = fmaf(hx, cc.x, fmaf(-hy, cc.y, tr.x));
            wy[c * NA + a] = fmaf(hy, cc.x, fmaf( hx, cc.y, tr.y));
        }
    } else {
        const int k = (bid - 60) * 256 + threadIdx.x;  // < 36864 exactly
        const float p = pd[k];
        g_invpd[k] = 1.0f / p;
        g_pd2[k]   = p * p;
    }
}

// ---- pairs: upper-triangular 32x32 tiles, mirrored via smem transpose ----
__global__ void __launch_bounds__(THREADS)
pairs_kernel(float* __restrict__ out)
{
    const int t   = blockIdx.y;
    const int tid = threadIdx.x;

    __shared__ __align__(16) float s[2 * PLANE];   // 7.5 KB: wx then wy
    __shared__ float tpen[32 * TP];                // transposed penalty tile
    __shared__ float tmsk[32 * TP];                // transposed mask tile
    const float* __restrict__ swx = s;
    const float* __restrict__ swy = s + PLANE;

    {
        const float4* __restrict__ src = reinterpret_cast<const float4*>(g_w + (size_t)t * 2 * PLANE);
        float4* dst = reinterpret_cast<float4*>(s);
        #pragma unroll
        for (int k = tid; k < 2 * PLANE / 4; k += THREADS) dst[k] = src[k];
    }
    __syncthreads();

    const int bi = c_bi[blockIdx.x];
    const int bj = c_bj[blockIdx.x];
    const int r  = tid >> 3;          // local i row 0..31
    const int q  = tid & 7;           // quad column 0..7
    const int i  = bi * 32 + r;
    const int j0 = bj * 32 + q * 4;

    // packed {-xi,-xi},{-yi,-yi} per circle
    unsigned long long nxi[NC], nyi[NC];
    #pragma unroll
    for (int c = 0; c < NC; ++c) {
        PACK_NEG2(nxi[c], swx[c * NA + i]);
        PACK_NEG2(nyi[c], swy[c * NA + i]);
    }

    // scalar min accumulators split by c-parity: shorter RAW chains
    float m0a = 3.4e38f, m1a = 3.4e38f, m2a = 3.4e38f, m3a = 3.4e38f;
    float m0b = 3.4e38f, m1b = 3.4e38f, m2b = 3.4e38f, m3b = 3.4e38f;

    #pragma unroll
    for (int d = 0; d < NC; ++d) {
        const ulonglong2 xj = *reinterpret_cast<const ulonglong2*>(swx + d * NA + j0);
        const ulonglong2 yj = *reinterpret_cast<const ulonglong2*>(swy + d * NA + j0);
        #pragma unroll
        for (int c = 0; c < NC; ++c) {
            if (c & 1) {
                CIRC2(m0b, m1b, xj.x, nxi[c], yj.x, nyi[c]);
                CIRC2(m2b, m3b, xj.y, nxi[c], yj.y, nyi[c]);
            } else {
                CIRC2(m0a, m1a, xj.x, nxi[c], yj.x, nyi[c]);
                CIRC2(m2a, m3a, xj.y, nxi[c], yj.y, nyi[c]);
            }
        }
    }

    float mv[4];
    mv[0] = fminf(m0a, m0b);
    mv[1] = fminf(m1a, m1b);
    mv[2] = fminf(m2a, m2b);
    mv[3] = fminf(m3a, m3b);

    const int idx = i * NA + j0;
    const float4 ip4 = *reinterpret_cast<const float4*>(g_invpd + idx);
    const float4 p24 = *reinterpret_cast<const float4*>(g_pd2 + idx);
    const float ipv[4] = {ip4.x, ip4.y, ip4.z, ip4.w};
    const float p2v[4] = {p24.x, p24.y, p24.z, p24.w};

    float4 pen, msk;
    float* penp = &pen.x;
    float* mskp = &msk.x;
    #pragma unroll
    for (int k = 0; k < 4; ++k) {
        const float m2e = mv[k] + 1e-30f;      // diagonal-zero guard for rsqrt
        float rr;
        asm("rsqrt.approx.f32 %0, %1;" : "=f"(rr) : "f"(m2e));
        const float mind = m2e * rr;           // = sqrt(m2e)
        penp[k] = fmaf(-mind, ipv[k], 1.0f);
        // sqrt monotone: mind <= p  <=>  m2 <= p^2 ; diagonal excluded by i != j
        mskp[k] = (mv[k] <= p2v[k] && i != j0 + k) ? 1.0f : 0.0f;
        // stage transposed (conflict-free: (4q+k)+r distinct mod 32)
        tpen[(q * 4 + k) * TP + r] = penp[k];
        tmsk[(q * 4 + k) * TP + r] = mskp[k];
    }

    const size_t tbase = (size_t)t * (NA * NA);
    const size_t moff  = (size_t)TT * (NA * NA);

    // direct tile write
    *reinterpret_cast<float4*>(out + tbase + idx) = pen;
    *reinterpret_cast<float4*>(out + moff + tbase + idx) = msk;

    __syncthreads();

    // mirrored tile write: rows = local j, cols = local i
    {
        float4 vp, vm;
        float* vpp = &vp.x;
        float* vmp = &vm.x;
        #pragma unroll
        for (int k = 0; k < 4; ++k) {
            vpp[k] = tpen[r * TP + q * 4 + k];
            vmp[k] = tmsk[r * TP + q * 4 + k];
        }
        const int ot = (bj * 32 + r) * NA + bi * 32 + q * 4;
        *reinterpret_cast<float4*>(out + tbase + ot) = vp;
        *reinterpret_cast<float4*>(out + moff + tbase + ot) = vm;
    }
}

extern "C" void kernel_launch(void* const* d_in, const int* in_sizes, int n_in,
                              void* d_out, int out_size)
{
    const float* traj = (const float*)d_in[0];   // (192,80,4)
    const float* cent = (const float*)d_in[1];   // (192,5,4)
    const float* pd   = (const float*)d_in[2];   // (192,192)

    prep_kernel<<<204, 256>>>(traj, cent, pd);

    dim3 grid(NTILE, TT);   // (21, 80)
    pairs_kernel<<<grid, THREADS>>>((float*)d_out);
}